// round 13
// baseline (speedup 1.0000x reference)
#include <cuda_runtime.h>

#define EPS 0.001f
#define TS 9   // table stride in floats (odd -> <=2-way LDS bank conflicts)
typedef unsigned long long u64;

// ---- packed f32x2 helpers (sm_100+) ----
__device__ __forceinline__ u64 pk2(float lo, float hi) {
    u64 r; asm("mov.b64 %0,{%1,%2};" : "=l"(r) : "f"(lo), "f"(hi)); return r;
}
__device__ __forceinline__ void upk2(u64 v, float& lo, float& hi) {
    asm("mov.b64 {%0,%1},%2;" : "=f"(lo), "=f"(hi) : "l"(v));
}
__device__ __forceinline__ u64 ffma2(u64 a, u64 b, u64 c) {
    u64 d; asm("fma.rn.f32x2 %0,%1,%2,%3;" : "=l"(d) : "l"(a), "l"(b), "l"(c)); return d;
}
__device__ __forceinline__ u64 fmul2(u64 a, u64 b) {
    u64 d; asm("mul.rn.f32x2 %0,%1,%2;" : "=l"(d) : "l"(a), "l"(b)); return d;
}
__device__ __forceinline__ u64 fadd2(u64 a, u64 b) {
    u64 d; asm("add.rn.f32x2 %0,%1,%2;" : "=l"(d) : "l"(a), "l"(b)); return d;
}

struct W1p { u64 c0[3], c1[3], bp[3]; };  // W1 columns / b1, packed over j-pairs

// Per-mask table entry (9 floats):
//  [0..3] S00 S01 S10 S11  (pre-mask Jacobian of s3 wrt q)
//  [4..5] sb0 sb1          (s3 = S q + sb)
//  [6..7] E0 E1            (dlo_dq; lo = E q + lb)
//  [8]    lb

// Per-row front end: z (packed over j-pairs), ReLU mask, g accumulation.
__device__ __forceinline__ void row_front(
    float q0, float q1, const W1p& w, const float* __restrict__ w2r,
    float gb0, float gb1, int& mask, float& g0, float& g1)
{
    const u64 q0p = pk2(q0, q0), q1p = pk2(q1, q1);
    float z[6];
    upk2(ffma2(w.c0[0], q0p, ffma2(w.c1[0], q1p, w.bp[0])), z[0], z[1]);
    upk2(ffma2(w.c0[1], q0p, ffma2(w.c1[1], q1p, w.bp[1])), z[2], z[3]);
    upk2(ffma2(w.c0[2], q0p, ffma2(w.c1[2], q1p, w.bp[2])), z[4], z[5]);

    unsigned nmask = 0;
    g0 = gb0; g1 = gb1;
#pragma unroll
    for (int j = 0; j < 6; j++) {
        nmask |= (__float_as_uint(z[j]) & 0x80000000u) >> (31 - j);
        float h = fmaxf(z[j], 0.0f);
        g0 = fmaf(w2r[j],     h, g0);
        g1 = fmaf(w2r[6 + j], h, g1);
    }
    mask = (int)(nmask ^ 0x3Fu);
}

// Packed (rowA,rowB) tail: table regs + inputs packed, one f32x2 stream.
__device__ __forceinline__ void pair_tail(
    u64 q0p, u64 q1p, u64 qd0p, u64 qd1p, u64 qdd0p, u64 qdd1p,
    const float* __restrict__ eA, const float* __restrict__ eB,
    u64 g0p, u64 g1p, u64& t0p, u64& t1p)
{
    // Pack table values across rows
    const u64 S00p = pk2(eA[0], eB[0]);
    const u64 S01p = pk2(eA[1], eB[1]);
    const u64 S10p = pk2(eA[2], eB[2]);
    const u64 S11p = pk2(eA[3], eB[3]);
    const u64 sb0p = pk2(eA[4], eB[4]);
    const u64 sb1p = pk2(eA[5], eB[5]);
    const u64 E0p  = pk2(eA[6], eB[6]);
    const u64 E1p  = pk2(eA[7], eB[7]);
    const u64 lbp  = pk2(eA[8], eB[8]);

    const u64 s30p = ffma2(S00p, q0p, ffma2(S01p, q1p, sb0p));
    const u64 s31p = ffma2(S10p, q0p, ffma2(S11p, q1p, sb1p));
    const u64 cp   = ffma2(E0p,  q0p, ffma2(E1p,  q1p, lbp));

    float s30A, s30B, s31A, s31B;
    upk2(s30p, s30A, s30B);
    upk2(s31p, s31A, s31B);

    const u64 ap  = pk2(fmaxf(s30A, 0.0f), fmaxf(s30B, 0.0f));
    const u64 bp  = pk2(fmaxf(s31A, 0.0f), fmaxf(s31B, 0.0f));
    const u64 m0p = pk2(s30A > 0.0f ? 1.0f : 0.0f, s30B > 0.0f ? 1.0f : 0.0f);
    const u64 m1p = pk2(s31A > 0.0f ? 1.0f : 0.0f, s31B > 0.0f ? 1.0f : 0.0f);

    const u64 d00p = fmul2(S00p, m0p);
    const u64 d01p = fmul2(S01p, m0p);
    const u64 d10p = fmul2(S10p, m1p);
    const u64 d11p = fmul2(S11p, m1p);

    const u64 dap = ffma2(d00p, qd0p, fmul2(d01p, qd1p));
    const u64 dbp = ffma2(d10p, qd0p, fmul2(d11p, qd1p));
    const u64 dcp = ffma2(E0p,  qd0p, fmul2(E1p,  qd1p));

    const u64 epsp = pk2(EPS, EPS);
    const u64 Lq0p = fmul2(ap, qdd0p);
    const u64 Lq1p = ffma2(cp, qdd0p, fmul2(bp, qdd1p));
    const u64 Hq0p = ffma2(ap, Lq0p, ffma2(cp, Lq1p, fmul2(epsp, qdd0p)));
    const u64 Hq1p = ffma2(bp, Lq1p, fmul2(epsp, qdd1p));

    const u64 adap  = fmul2(ap, dap);
    const u64 dh01p = ffma2(ap, dcp, fmul2(cp, dap));
    const u64 dHq0p = ffma2(fadd2(adap, adap), qd0p, fmul2(dh01p, qd1p));
    const u64 cdbp  = ffma2(cp, dcp, fmul2(bp, dbp));
    const u64 dHq1p = ffma2(dh01p, qd0p, fmul2(fadd2(cdbp, cdbp), qd1p));

    const u64 Ltq0p = ffma2(ap, qd0p, fmul2(cp, qd1p));
    const u64 Ltq1p = fmul2(bp, qd1p);
    const u64 tw0p  = fadd2(Ltq0p, Ltq0p);
    const u64 tw1p  = fadd2(Ltq1p, Ltq1p);
    const u64 P0p   = fmul2(tw0p, qd0p);
    const u64 P1p   = fmul2(tw0p, qd1p);
    const u64 P2p   = fmul2(tw1p, qd1p);

    const u64 base0p = fadd2(fadd2(Hq0p, dHq0p), g0p);
    const u64 base1p = fadd2(fadd2(Hq1p, dHq1p), g1p);
    t0p = ffma2(d00p, P0p, ffma2(E0p, P1p, ffma2(d10p, P2p, base0p)));
    t1p = ffma2(d01p, P0p, ffma2(E1p, P1p, ffma2(d11p, P2p, base1p)));
}

__global__ void __launch_bounds__(128, 6)
lnn_tau_kernel(const float* __restrict__ x,
               const float* __restrict__ W1, const float* __restrict__ b1,
               const float* __restrict__ W2, const float* __restrict__ b2,
               const float* __restrict__ W3, const float* __restrict__ b3,
               const float* __restrict__ W4, const float* __restrict__ b4,
               float* __restrict__ out, int n)
{
    __shared__ float tab[64 * TS];

    // Build the 64-entry mask table (S, sb, E, lb).
    if (threadIdx.x < 64) {
        const int m = threadIdx.x;
        float S00 = 0.f, S01 = 0.f, S10 = 0.f, S11 = 0.f;
        float sb0 = b3[0], sb1 = b3[1];
        float E0 = 0.f, E1 = 0.f, lb = b4[0];
#pragma unroll
        for (int j = 0; j < 6; j++) {
            if ((m >> j) & 1) {
                const float a0 = W1[2 * j], a1 = W1[2 * j + 1], bb = b1[j];
                const float w30 = W3[j], w31 = W3[6 + j], w4j = W4[j];
                S00 = fmaf(w30, a0, S00); S01 = fmaf(w30, a1, S01); sb0 = fmaf(w30, bb, sb0);
                S10 = fmaf(w31, a0, S10); S11 = fmaf(w31, a1, S11); sb1 = fmaf(w31, bb, sb1);
                E0  = fmaf(w4j, a0, E0);  E1  = fmaf(w4j, a1, E1);  lb  = fmaf(w4j, bb, lb);
            }
        }
        float* e = tab + m * TS;
        e[0] = S00; e[1] = S01; e[2] = S10; e[3] = S11;
        e[4] = sb0; e[5] = sb1;
        e[6] = E0;  e[7] = E1;  e[8] = lb;
    }

    // Per-thread weight registers, loaded ONCE, amortized over the grid-stride loop.
    W1p w;
#pragma unroll
    for (int p = 0; p < 3; p++) {
        w.c0[p] = pk2(__ldg(W1 + 4 * p),     __ldg(W1 + 4 * p + 2));
        w.c1[p] = pk2(__ldg(W1 + 4 * p + 1), __ldg(W1 + 4 * p + 3));
        w.bp[p] = pk2(__ldg(b1 + 2 * p),     __ldg(b1 + 2 * p + 1));
    }
    float w2r[12];
#pragma unroll
    for (int j = 0; j < 6; j++) {
        w2r[j]     = __ldg(W2 + j);
        w2r[6 + j] = __ldg(W2 + 6 + j);
    }
    const float gb0 = __ldg(b2 + 0);
    const float gb1 = __ldg(b2 + 1);
    __syncthreads();

    const int np = n >> 1;  // pairs of rows
    const int stride = gridDim.x * blockDim.x;

    for (int p = blockIdx.x * blockDim.x + threadIdx.x; p < np; p += stride) {
        const float4* xp = reinterpret_cast<const float4*>(x + (size_t)p * 12);
        const float4 u0 = xp[0], u1 = xp[1], u2 = xp[2];
        // rowA = (u0.x,u0.y | u0.z,u0.w | u1.x,u1.y)
        // rowB = (u1.z,u1.w | u2.x,u2.y | u2.z,u2.w)

        int maskA, maskB;
        float g0A, g1A, g0B, g1B;
        row_front(u0.x, u0.y, w, w2r, gb0, gb1, maskA, g0A, g1A);
        row_front(u1.z, u1.w, w, w2r, gb0, gb1, maskB, g0B, g1B);

        const float* eA = tab + maskA * TS;
        const float* eB = tab + maskB * TS;

        const u64 q0p   = pk2(u0.x, u1.z);
        const u64 q1p   = pk2(u0.y, u1.w);
        const u64 qd0p  = pk2(u0.z, u2.x);
        const u64 qd1p  = pk2(u0.w, u2.y);
        const u64 qdd0p = pk2(u1.x, u2.z);
        const u64 qdd1p = pk2(u1.y, u2.w);
        const u64 g0p   = pk2(g0A, g0B);
        const u64 g1p   = pk2(g1A, g1B);

        u64 t0p, t1p;
        pair_tail(q0p, q1p, qd0p, qd1p, qdd0p, qdd1p, eA, eB, g0p, g1p, t0p, t1p);

        float t0A, t0B, t1A, t1B;
        upk2(t0p, t0A, t0B);
        upk2(t1p, t1A, t1B);
        reinterpret_cast<float4*>(out)[p] = make_float4(t0A, t1A, t0B, t1B);
    }

    // Tail (n odd) — n is even here; kept for safety (duplicate row in both lanes).
    if ((n & 1) && blockIdx.x == 0 && threadIdx.x == 0) {
        const int row = n - 1;
        const float* xr = x + (size_t)row * 6;
        int mask; float g0, g1;
        row_front(xr[0], xr[1], w, w2r, gb0, gb1, mask, g0, g1);
        const float* e = tab + mask * TS;
        u64 t0p, t1p;
        pair_tail(pk2(xr[0], xr[0]), pk2(xr[1], xr[1]),
                  pk2(xr[2], xr[2]), pk2(xr[3], xr[3]),
                  pk2(xr[4], xr[4]), pk2(xr[5], xr[5]),
                  e, e, pk2(g0, g0), pk2(g1, g1), t0p, t1p);
        float t0, t1, dum;
        upk2(t0p, t0, dum);
        upk2(t1p, t1, dum);
        out[(size_t)row * 2 + 0] = t0;
        out[(size_t)row * 2 + 1] = t1;
    }
}

extern "C" void kernel_launch(void* const* d_in, const int* in_sizes, int n_in,
                              void* d_out, int out_size)
{
    const float* x  = (const float*)d_in[0];
    const float* W1 = (const float*)d_in[1];
    const float* b1 = (const float*)d_in[2];
    const float* W2 = (const float*)d_in[3];
    const float* b2 = (const float*)d_in[4];
    const float* W3 = (const float*)d_in[5];
    const float* b3 = (const float*)d_in[6];
    const float* W4 = (const float*)d_in[7];
    const float* b4 = (const float*)d_in[8];
    float* out = (float*)d_out;

    const int n = in_sizes[0] / 6;   // rows

    // Persistent-style grid: 6 blocks/SM resident, grid-stride (~9 iters/thread)
    const int threads = 128;
    const int blocks = 148 * 6;
    lnn_tau_kernel<<<blocks, threads>>>(x, W1, b1, W2, b2, W3, b3, W4, b4, out, n);
}